// round 6
// baseline (speedup 1.0000x reference)
#include <cuda_runtime.h>
#include <cuda_bf16.h>
#include <cstdint>
#include <math.h>

#define B_ 4
#define S_ 2048
#define DM_ 512
#define H_ 8
#define D_ 64
#define LEFT_ 128
#define RIGHT_ 128
#define M_ (B_ * S_)

// Scratch (device globals: allocation-free rule)
__device__ float g_Q[M_ * DM_];
__device__ float g_K[M_ * DM_];
__device__ float g_V[M_ * DM_];
__device__ float g_ctx[M_ * DM_];
__device__ float g_vmean[B_ * H_ * D_];
// Pre-split bf16 operands: [row][ hi(512) | lo(512) ]
__device__ __nv_bfloat16 g_x2[M_ * 1024];
__device__ __nv_bfloat16 g_ctx2[M_ * 1024];
// Weights transposed+split: [w][n][ hi(512) | lo(512) ]
__device__ __nv_bfloat16 g_W2[4 * DM_ * 1024];

__device__ __forceinline__ uint32_t smem_u32(const void* p) {
    uint32_t a;
    asm("{ .reg .u64 t; cvta.to.shared.u64 t, %1; cvt.u32.u64 %0, t; }"
        : "=r"(a) : "l"(p));
    return a;
}
__device__ __forceinline__ void cp16(uint32_t s, const void* g) {
    asm volatile("cp.async.cg.shared.global [%0], [%1], 16;"
                 :: "r"(s), "l"(g) : "memory");
}
#define CP_COMMIT() asm volatile("cp.async.commit_group;" ::: "memory")
#define CP_WAIT(n)  asm volatile("cp.async.wait_group %0;" :: "n"(n) : "memory")

__device__ __forceinline__ void bf16_split(float x0, float x1,
                                           uint32_t& hi, uint32_t& lo) {
    __nv_bfloat162 h = __float22bfloat162_rn(make_float2(x0, x1));
    float2 f = __bfloat1622float2(h);
    __nv_bfloat162 l = __float22bfloat162_rn(make_float2(x0 - f.x, x1 - f.y));
    hi = *reinterpret_cast<uint32_t*>(&h);
    lo = *reinterpret_cast<uint32_t*>(&l);
}

__device__ __forceinline__ void mma_bf16(float* c, const uint32_t* a,
                                         const uint32_t* b) {
    asm volatile(
        "mma.sync.aligned.m16n8k16.row.col.f32.bf16.bf16.f32 "
        "{%0,%1,%2,%3}, {%4,%5,%6,%7}, {%8,%9}, {%0,%1,%2,%3};"
        : "+f"(c[0]), "+f"(c[1]), "+f"(c[2]), "+f"(c[3])
        : "r"(a[0]), "r"(a[1]), "r"(a[2]), "r"(a[3]), "r"(b[0]), "r"(b[1]));
}

// ===========================================================================
// Split kernels
// ===========================================================================
// fp32 [M][512] -> bf16 [M][ hi512 | lo512 ]
__global__ __launch_bounds__(256) void split_a(const float* __restrict__ src,
                                               __nv_bfloat16* __restrict__ dst)
{
    int idx = (blockIdx.x * 256 + threadIdx.x) * 4;
    int row = idx >> 9, k = idx & 511;
    float4 v = *reinterpret_cast<const float4*>(&src[idx]);
    uint32_t h0, l0, h1, l1;
    bf16_split(v.x, v.y, h0, l0);
    bf16_split(v.z, v.w, h1, l1);
    *reinterpret_cast<uint2*>(&dst[row * 1024 + k]) = make_uint2(h0, h1);
    *reinterpret_cast<uint2*>(&dst[row * 1024 + 512 + k]) = make_uint2(l0, l1);
}

// W[512][512] -> W2t[n][ hi(k) | lo(k) ], tiled transpose
__global__ __launch_bounds__(256) void split_w(
    const float* __restrict__ W0, const float* __restrict__ W1,
    const float* __restrict__ W2p, const float* __restrict__ W3)
{
    __shared__ float t[32][33];
    const float* W = (blockIdx.z == 0) ? W0 : (blockIdx.z == 1) ? W1
                   : (blockIdx.z == 2) ? W2p : W3;
    __nv_bfloat16* dst = g_W2 + blockIdx.z * DM_ * 1024;
    int bx = blockIdx.x * 32;   // k tile
    int by = blockIdx.y * 32;   // n tile
    int tx = threadIdx.x & 31, ty = threadIdx.x >> 5;
    #pragma unroll
    for (int i = 0; i < 4; i++)
        t[ty + i * 8][tx] = W[(bx + ty + i * 8) * DM_ + by + tx];
    __syncthreads();
    #pragma unroll
    for (int i = 0; i < 4; i++) {
        int n = by + ty + i * 8;
        int k = bx + tx;
        float v = t[tx][ty + i * 8];
        __nv_bfloat16 h = __float2bfloat16_rn(v);
        __nv_bfloat16 l = __float2bfloat16_rn(v - __bfloat162float(h));
        dst[n * 1024 + k] = h;
        dst[n * 1024 + 512 + k] = l;
    }
}

// ===========================================================================
// Pure-bf16 GEMM, K'=1536 (3 regions: AhBh, AhBl, AlBh), cp.async 4-stage.
// CTA 128x128, warp 32x64, BK=32, 256 threads, 2 CTAs/SM.
// ===========================================================================
#define KSTRB 80
#define ASTG 10240               // 128 rows * 80 B
#define STG 20480                // A + B
#define NST 4
#define GEMM_SMEM_BYTES (NST * STG)   // 81920
#define NCHUNK 48

__device__ __forceinline__ void issue_chunk(
    uint32_t sbase, const __nv_bfloat16* __restrict__ A2,
    const __nv_bfloat16* __restrict__ Bt,
    int bm, int bn, int c, int stage, int tid)
{
    const int r = c >> 4;
    const int kk = (c & 15) << 5;
    const int ab = kk + ((r == 2) ? 512 : 0);
    const int bb = kk + ((r == 1) ? 512 : 0);
    const int row = tid >> 1, h = tid & 1;
    const __nv_bfloat16* ga = &A2[(bm + row) * 1024 + ab + h * 16];
    const __nv_bfloat16* gb = &Bt[(bn + row) * 1024 + bb + h * 16];
    uint32_t sa = sbase + stage * STG + row * KSTRB + h * 32;
    uint32_t sb = sa + ASTG;
    cp16(sa, ga); cp16(sa + 16, ga + 8);
    cp16(sb, gb); cp16(sb + 16, gb + 8);
}

__device__ __forceinline__ void gemm_bf16_body(
    const __nv_bfloat16* __restrict__ A2, const __nv_bfloat16* __restrict__ Bt,
    const float* __restrict__ bias, float* __restrict__ C, int bm, int bn)
{
    extern __shared__ char smc[];
    const uint32_t sbase = smem_u32(smc);
    const int tid = threadIdx.x;
    const int wid = tid >> 5, lane = tid & 31;
    const int g = lane >> 2, tg = lane & 3;
    const int wm = (wid & 3) * 32, wn = (wid >> 2) * 64;

    // Prologue: stages 0..2
    #pragma unroll
    for (int p = 0; p < 3; p++) {
        issue_chunk(sbase, A2, Bt, bm, bn, p, p, tid);
        CP_COMMIT();
    }

    float acc[2][8][4] = {};

    for (int c = 0; c < NCHUNK; c++) {
        if (c <= NCHUNK - 3)      CP_WAIT(2);
        else if (c == NCHUNK - 2) CP_WAIT(1);
        else                      CP_WAIT(0);
        __syncthreads();
        if (c + 3 < NCHUNK) {
            issue_chunk(sbase, A2, Bt, bm, bn, c + 3, (c + 3) & 3, tid);
            CP_COMMIT();
        }

        char* pA = smc + (c & 3) * STG;
        char* pB = pA + ASTG;
        #pragma unroll
        for (int ks = 0; ks < 2; ks++) {
            const int kb = ks * 32 + tg * 4;
            uint32_t Af[2][4];
            #pragma unroll
            for (int mt = 0; mt < 2; mt++) {
                const int r0 = wm + mt * 16 + g;
                Af[mt][0] = *reinterpret_cast<uint32_t*>(pA + r0 * KSTRB + kb);
                Af[mt][1] = *reinterpret_cast<uint32_t*>(pA + (r0 + 8) * KSTRB + kb);
                Af[mt][2] = *reinterpret_cast<uint32_t*>(pA + r0 * KSTRB + kb + 16);
                Af[mt][3] = *reinterpret_cast<uint32_t*>(pA + (r0 + 8) * KSTRB + kb + 16);
            }
            #pragma unroll
            for (int nt = 0; nt < 8; nt++) {
                const int n = wn + nt * 8 + g;
                uint32_t Bf[2];
                Bf[0] = *reinterpret_cast<uint32_t*>(pB + n * KSTRB + kb);
                Bf[1] = *reinterpret_cast<uint32_t*>(pB + n * KSTRB + kb + 16);
                #pragma unroll
                for (int mt = 0; mt < 2; mt++)
                    mma_bf16(acc[mt][nt], Af[mt], Bf);
            }
        }
    }

    // Epilogue
    #pragma unroll
    for (int mt = 0; mt < 2; mt++) {
        const int row0 = bm + wm + mt * 16 + g;
        #pragma unroll
        for (int nt = 0; nt < 8; nt++) {
            const int col = bn + wn + nt * 8 + tg * 2;
            float2 b2 = *reinterpret_cast<const float2*>(&bias[col]);
            float2 o0, o1;
            o0.x = acc[mt][nt][0] + b2.x;
            o0.y = acc[mt][nt][1] + b2.y;
            o1.x = acc[mt][nt][2] + b2.x;
            o1.y = acc[mt][nt][3] + b2.y;
            *reinterpret_cast<float2*>(&C[row0 * DM_ + col]) = o0;
            *reinterpret_cast<float2*>(&C[(row0 + 8) * DM_ + col]) = o1;
        }
    }
}

__global__ __launch_bounds__(256, 2) void qkv_gemm_tc(
    const float* __restrict__ bq, const float* __restrict__ bk,
    const float* __restrict__ bv)
{
    const float* bias; float* C;
    if (blockIdx.z == 0)      { bias = bq; C = g_Q; }
    else if (blockIdx.z == 1) { bias = bk; C = g_K; }
    else                      { bias = bv; C = g_V; }
    gemm_bf16_body(g_x2, g_W2 + blockIdx.z * DM_ * 1024, bias, C,
                   blockIdx.y * 128, blockIdx.x * 128);
}

__global__ __launch_bounds__(256, 2) void out_gemm_tc(
    const float* __restrict__ bo, float* __restrict__ out)
{
    gemm_bf16_body(g_ctx2, g_W2 + 3 * DM_ * 1024, bo, out,
                   blockIdx.y * 128, blockIdx.x * 128);
}

// ===========================================================================
// Per-(b,h) mean of V (for fully-masked rows: uniform softmax over all keys)
// ===========================================================================
__global__ __launch_bounds__(512) void vmean_kernel()
{
    __shared__ float red[8][64];
    const int bh = blockIdx.x;
    const int b = bh / H_, h = bh % H_;
    const int d = threadIdx.x & 63;
    const int c = threadIdx.x >> 6;
    float s = 0.f;
    const int j0 = c * (S_ / 8);
    #pragma unroll 4
    for (int j = j0; j < j0 + S_ / 8; j++)
        s += g_V[(b * S_ + j) * DM_ + h * D_ + d];
    red[c][d] = s;
    __syncthreads();
    if (c == 0) {
        float t = 0.f;
        #pragma unroll
        for (int k = 0; k < 8; k++) t += red[k][d];
        g_vmean[bh * D_ + d] = t * (1.0f / S_);
    }
}

// ===========================================================================
// Banded attention (unchanged)
// ===========================================================================
#define SQ_STR 65
#define SKV_STR 65
#define SS_STR 321
#define ATTN_SMEM_BYTES ((64 * SQ_STR + 64 * SS_STR + 64 * SKV_STR) * 4)

__global__ __launch_bounds__(256) void attn_kernel(const int* __restrict__ x_len)
{
    const int q0 = blockIdx.x * 64;
    const int h  = blockIdx.y;
    const int b  = blockIdx.z;
    const int tid = threadIdx.x;
    const int tx = tid & 15, ty = tid >> 4;
    const int wid = tid >> 5, lane = tid & 31;
    const int xlen = x_len[b];

    extern __shared__ float sm[];
    float* sQ  = sm;
    float* sS  = sQ + 64 * SQ_STR;
    float* sKV = sS + 64 * SS_STR;
    __shared__ int sEmpty[64];

    const int j_lo = max(0, q0 - LEFT_);
    const int j_hi = min(S_ - 1, q0 + 63 + RIGHT_);
    const int KT = j_hi - j_lo + 1;
    const int NC = KT >> 6;

    #pragma unroll
    for (int l = 0; l < 4; l++) {
        int v = tid + l * 256;
        int r = v >> 4, c4 = (v & 15) << 2;
        float4 q4 = *reinterpret_cast<const float4*>(
            &g_Q[(b * S_ + q0 + r) * DM_ + h * D_ + c4]);
        float* dst = &sQ[r * SQ_STR + c4];
        dst[0] = q4.x; dst[1] = q4.y; dst[2] = q4.z; dst[3] = q4.w;
    }

    for (int c = 0; c < NC; c++) {
        #pragma unroll
        for (int l = 0; l < 4; l++) {
            int v = tid + l * 256;
            int r = v >> 4, c4 = (v & 15) << 2;
            int j = j_lo + c * 64 + r;
            float4 k4 = *reinterpret_cast<const float4*>(
                &g_K[(b * S_ + j) * DM_ + h * D_ + c4]);
            float* dst = &sKV[r * SKV_STR + c4];
            dst[0] = k4.x; dst[1] = k4.y; dst[2] = k4.z; dst[3] = k4.w;
        }
        __syncthreads();
        float acc[4][4] = {};
        #pragma unroll 8
        for (int d = 0; d < 64; d++) {
            float a[4], kk[4];
            #pragma unroll
            for (int i = 0; i < 4; i++) a[i] = sQ[(ty * 4 + i) * SQ_STR + d];
            #pragma unroll
            for (int j = 0; j < 4; j++) kk[j] = sKV[(tx * 4 + j) * SKV_STR + d];
            #pragma unroll
            for (int i = 0; i < 4; i++)
                #pragma unroll
                for (int j = 0; j < 4; j++)
                    acc[i][j] += a[i] * kk[j];
        }
        #pragma unroll
        for (int i = 0; i < 4; i++)
            #pragma unroll
            for (int j = 0; j < 4; j++)
                sS[(ty * 4 + i) * SS_STR + c * 64 + tx * 4 + j] = acc[i][j] * 0.125f;
        __syncthreads();
    }

    for (int r = wid; r < 64; r += 8) {
        int iq = q0 + r;
        int lo = max(0, iq - LEFT_);
        int hi = min(S_ - 1, iq + RIGHT_);
        int vh = min(hi, xlen - 1);
        float* row = &sS[r * SS_STR];
        int llo = lo - j_lo, lhi = vh - j_lo;
        if (lhi < llo) {
            if (lane == 0) sEmpty[r] = 1;
            for (int k = lane; k < KT; k += 32) row[k] = 0.f;
        } else {
            if (lane == 0) sEmpty[r] = 0;
            float mx = -3.4e38f;
            for (int k = llo + lane; k <= lhi; k += 32) mx = fmaxf(mx, row[k]);
            #pragma unroll
            for (int o = 16; o; o >>= 1) mx = fmaxf(mx, __shfl_xor_sync(~0u, mx, o));
            float sum = 0.f;
            for (int k = llo + lane; k <= lhi; k += 32) {
                float e = __expf(row[k] - mx);
                row[k] = e; sum += e;
            }
            #pragma unroll
            for (int o = 16; o; o >>= 1) sum += __shfl_xor_sync(~0u, sum, o);
            float inv = 1.0f / sum;
            __syncwarp();
            for (int k = lane; k < KT; k += 32)
                row[k] = (k >= llo && k <= lhi) ? row[k] * inv : 0.f;
        }
    }
    __syncthreads();

    float acc2[4][4] = {};
    for (int c = 0; c < NC; c++) {
        #pragma unroll
        for (int l = 0; l < 4; l++) {
            int v = tid + l * 256;
            int r = v >> 4, c4 = (v & 15) << 2;
            int j = j_lo + c * 64 + r;
            float4 v4 = *reinterpret_cast<const float4*>(
                &g_V[(b * S_ + j) * DM_ + h * D_ + c4]);
            float* dst = &sKV[r * SKV_STR + c4];
            dst[0] = v4.x; dst[1] = v4.y; dst[2] = v4.z; dst[3] = v4.w;
        }
        __syncthreads();
        #pragma unroll 8
        for (int kk = 0; kk < 64; kk++) {
            float a[4], vv[4];
            #pragma unroll
            for (int i = 0; i < 4; i++) a[i] = sS[(ty * 4 + i) * SS_STR + c * 64 + kk];
            #pragma unroll
            for (int j = 0; j < 4; j++) vv[j] = sKV[kk * SKV_STR + tx * 4 + j];
            #pragma unroll
            for (int i = 0; i < 4; i++)
                #pragma unroll
                for (int j = 0; j < 4; j++)
                    acc2[i][j] += a[i] * vv[j];
        }
        __syncthreads();
    }

    #pragma unroll
    for (int i = 0; i < 4; i++) {
        int r = ty * 4 + i, q = q0 + r;
        #pragma unroll
        for (int j = 0; j < 4; j++) {
            int d = tx * 4 + j;
            float addv = sEmpty[r] ? g_vmean[(b * H_ + h) * D_ + d] : 0.f;
            g_ctx[(b * S_ + q) * DM_ + h * D_ + d] = acc2[i][j] + addv;
        }
    }
}

// ---------------------------------------------------------------------------
extern "C" void kernel_launch(void* const* d_in, const int* in_sizes, int n_in,
                              void* d_out, int out_size)
{
    const float* x  = (const float*)d_in[0];
    const float* Wq = (const float*)d_in[1];
    const float* bq = (const float*)d_in[2];
    const float* Wk = (const float*)d_in[3];
    const float* bk = (const float*)d_in[4];
    const float* Wv = (const float*)d_in[5];
    const float* bv = (const float*)d_in[6];
    const float* Wo = (const float*)d_in[7];
    const float* bo = (const float*)d_in[8];
    const int* xlen = (const int*)d_in[9];
    float* out = (float*)d_out;

    void *px2, *pctx2, *pctx;
    cudaGetSymbolAddress(&px2, g_x2);
    cudaGetSymbolAddress(&pctx2, g_ctx2);
    cudaGetSymbolAddress(&pctx, g_ctx);

    cudaFuncSetAttribute(qkv_gemm_tc,
                         cudaFuncAttributeMaxDynamicSharedMemorySize,
                         GEMM_SMEM_BYTES);
    cudaFuncSetAttribute(out_gemm_tc,
                         cudaFuncAttributeMaxDynamicSharedMemorySize,
                         GEMM_SMEM_BYTES);
    cudaFuncSetAttribute(attn_kernel,
                         cudaFuncAttributeMaxDynamicSharedMemorySize,
                         ATTN_SMEM_BYTES);

    // Pre-split inputs + weights
    split_a<<<M_ * DM_ / 1024, 256>>>(x, (__nv_bfloat16*)px2);
    split_w<<<dim3(16, 16, 4), 256>>>(Wq, Wk, Wv, Wo);

    dim3 gqkv(DM_ / 128, M_ / 128, 3);
    qkv_gemm_tc<<<gqkv, 256, GEMM_SMEM_BYTES>>>(bq, bk, bv);

    vmean_kernel<<<B_ * H_, 512>>>();
    attn_kernel<<<dim3(S_ / 64, H_, B_), 256, ATTN_SMEM_BYTES>>>(xlen);

    split_a<<<M_ * DM_ / 1024, 256>>>((const float*)pctx, (__nv_bfloat16*)pctx2);
    out_gemm_tc<<<dim3(DM_ / 128, M_ / 128), 256, GEMM_SMEM_BYTES>>>(bo, out);
}

// round 10
// speedup vs baseline: 1.1053x; 1.1053x over previous
#include <cuda_runtime.h>
#include <cuda_bf16.h>
#include <cstdint>
#include <math.h>

#define B_ 4
#define S_ 2048
#define DM_ 512
#define H_ 8
#define D_ 64
#define LEFT_ 128
#define RIGHT_ 128
#define M_ (B_ * S_)

// Scratch (device globals: allocation-free rule)
// Split bf16 layout: [row][ hi(512) | lo(512) ]
__device__ __nv_bfloat16 g_x2[M_ * 1024];
__device__ __nv_bfloat16 g_Q2[M_ * 1024];
__device__ __nv_bfloat16 g_K2[M_ * 1024];
__device__ __nv_bfloat16 g_V2[M_ * 1024];
__device__ __nv_bfloat16 g_ctx2[M_ * 1024];
__device__ __nv_bfloat16 g_W2[4 * DM_ * 1024];   // [w][n][ hi(k) | lo(k) ]
__device__ float g_vmean[B_ * H_ * D_];
__device__ float g_vpart[B_ * H_ * 8 * 64];
__device__ float g_bqkv[3 * DM_];

__device__ __forceinline__ uint32_t smem_u32(const void* p) {
    uint32_t a;
    asm("{ .reg .u64 t; cvta.to.shared.u64 t, %1; cvt.u32.u64 %0, t; }"
        : "=r"(a) : "l"(p));
    return a;
}
__device__ __forceinline__ void cp16(uint32_t s, const void* g) {
    asm volatile("cp.async.cg.shared.global [%0], [%1], 16;"
                 :: "r"(s), "l"(g) : "memory");
}
#define CP_COMMIT() asm volatile("cp.async.commit_group;" ::: "memory")
#define CP_WAIT(n)  asm volatile("cp.async.wait_group %0;" :: "n"(n) : "memory")

__device__ __forceinline__ void bf16_split(float x0, float x1,
                                           uint32_t& hi, uint32_t& lo) {
    __nv_bfloat162 h = __float22bfloat162_rn(make_float2(x0, x1));
    float2 f = __bfloat1622float2(h);
    __nv_bfloat162 l = __float22bfloat162_rn(make_float2(x0 - f.x, x1 - f.y));
    hi = *reinterpret_cast<uint32_t*>(&h);
    lo = *reinterpret_cast<uint32_t*>(&l);
}

__device__ __forceinline__ void mma_bf16(float* c, const uint32_t* a,
                                         const uint32_t* b) {
    asm volatile(
        "mma.sync.aligned.m16n8k16.row.col.f32.bf16.bf16.f32 "
        "{%0,%1,%2,%3}, {%4,%5,%6,%7}, {%8,%9}, {%0,%1,%2,%3};"
        : "+f"(c[0]), "+f"(c[1]), "+f"(c[2]), "+f"(c[3])
        : "r"(a[0]), "r"(a[1]), "r"(a[2]), "r"(a[3]), "r"(b[0]), "r"(b[1]));
}

// ===========================================================================
// Split kernels
// ===========================================================================
__global__ __launch_bounds__(256) void split_a(const float* __restrict__ src,
                                               __nv_bfloat16* __restrict__ dst)
{
    int idx = (blockIdx.x * 256 + threadIdx.x) * 4;
    int row = idx >> 9, k = idx & 511;
    float4 v = *reinterpret_cast<const float4*>(&src[idx]);
    uint32_t h0, l0, h1, l1;
    bf16_split(v.x, v.y, h0, l0);
    bf16_split(v.z, v.w, h1, l1);
    *reinterpret_cast<uint2*>(&dst[row * 1024 + k]) = make_uint2(h0, h1);
    *reinterpret_cast<uint2*>(&dst[row * 1024 + 512 + k]) = make_uint2(l0, l1);
}

__global__ __launch_bounds__(256) void split_w(
    const float* __restrict__ W0, const float* __restrict__ W1,
    const float* __restrict__ W2p, const float* __restrict__ W3)
{
    __shared__ float t[32][33];
    const float* W = (blockIdx.z == 0) ? W0 : (blockIdx.z == 1) ? W1
                   : (blockIdx.z == 2) ? W2p : W3;
    __nv_bfloat16* dst = g_W2 + blockIdx.z * DM_ * 1024;
    int bx = blockIdx.x * 32;
    int by = blockIdx.y * 32;
    int tx = threadIdx.x & 31, ty = threadIdx.x >> 5;
    #pragma unroll
    for (int i = 0; i < 4; i++)
        t[ty + i * 8][tx] = W[(bx + ty + i * 8) * DM_ + by + tx];
    __syncthreads();
    #pragma unroll
    for (int i = 0; i < 4; i++) {
        int n = by + ty + i * 8;
        int k = bx + tx;
        float v = t[tx][ty + i * 8];
        __nv_bfloat16 h = __float2bfloat16_rn(v);
        __nv_bfloat16 l = __float2bfloat16_rn(v - __bfloat162float(h));
        dst[n * 1024 + k] = h;
        dst[n * 1024 + 512 + k] = l;
    }
}

__global__ void stage_bias(const float* bq, const float* bk, const float* bv)
{
    int i = threadIdx.x + blockIdx.x * 256;
    if (i < DM_) { g_bqkv[i] = bq[i]; g_bqkv[DM_ + i] = bk[i]; g_bqkv[2 * DM_ + i] = bv[i]; }
}

// ===========================================================================
// Pure-bf16 GEMM, K'=1536 (3 regions), cp.async 4-stage. CTA 128x128.
// Epilogue: SPLIT=true -> write hi/lo bf16; false -> fp32.
// ===========================================================================
#define KSTRB 80
#define ASTG 10240
#define STG 20480
#define GEMM_SMEM_BYTES (4 * STG)
#define NCHUNK 48

__device__ __forceinline__ void issue_chunk(
    uint32_t sbase, const __nv_bfloat16* __restrict__ A2,
    const __nv_bfloat16* __restrict__ Bt,
    int bm, int bn, int c, int stage, int tid)
{
    const int r = c >> 4;
    const int kk = (c & 15) << 5;
    const int ab = kk + ((r == 2) ? 512 : 0);
    const int bb = kk + ((r == 1) ? 512 : 0);
    const int row = tid >> 1, h = tid & 1;
    const __nv_bfloat16* ga = &A2[(bm + row) * 1024 + ab + h * 16];
    const __nv_bfloat16* gb = &Bt[(bn + row) * 1024 + bb + h * 16];
    uint32_t sa = sbase + stage * STG + row * KSTRB + h * 32;
    uint32_t sb = sa + ASTG;
    cp16(sa, ga); cp16(sa + 16, ga + 8);
    cp16(sb, gb); cp16(sb + 16, gb + 8);
}

template <bool SPLIT>
__device__ __forceinline__ void gemm_bf16_body(
    const __nv_bfloat16* __restrict__ A2, const __nv_bfloat16* __restrict__ Bt,
    const float* __restrict__ bias, float* __restrict__ C,
    __nv_bfloat16* __restrict__ C2, int bm, int bn)
{
    extern __shared__ char smc[];
    const uint32_t sbase = smem_u32(smc);
    const int tid = threadIdx.x;
    const int wid = tid >> 5, lane = tid & 31;
    const int g = lane >> 2, tg = lane & 3;
    const int wm = (wid & 3) * 32, wn = (wid >> 2) * 64;

    #pragma unroll
    for (int p = 0; p < 3; p++) {
        issue_chunk(sbase, A2, Bt, bm, bn, p, p, tid);
        CP_COMMIT();
    }

    float acc[2][8][4] = {};

    for (int c = 0; c < NCHUNK; c++) {
        if (c <= NCHUNK - 3)      CP_WAIT(2);
        else if (c == NCHUNK - 2) CP_WAIT(1);
        else                      CP_WAIT(0);
        __syncthreads();
        if (c + 3 < NCHUNK) {
            issue_chunk(sbase, A2, Bt, bm, bn, c + 3, (c + 3) & 3, tid);
            CP_COMMIT();
        }

        char* pA = smc + (c & 3) * STG;
        char* pB = pA + ASTG;
        #pragma unroll
        for (int ks = 0; ks < 2; ks++) {
            const int kb = ks * 32 + tg * 4;
            uint32_t Af[2][4];
            #pragma unroll
            for (int mt = 0; mt < 2; mt++) {
                const int r0 = wm + mt * 16 + g;
                Af[mt][0] = *reinterpret_cast<uint32_t*>(pA + r0 * KSTRB + kb);
                Af[mt][1] = *reinterpret_cast<uint32_t*>(pA + (r0 + 8) * KSTRB + kb);
                Af[mt][2] = *reinterpret_cast<uint32_t*>(pA + r0 * KSTRB + kb + 16);
                Af[mt][3] = *reinterpret_cast<uint32_t*>(pA + (r0 + 8) * KSTRB + kb + 16);
            }
            #pragma unroll
            for (int nt = 0; nt < 8; nt++) {
                const int n = wn + nt * 8 + g;
                uint32_t Bf[2];
                Bf[0] = *reinterpret_cast<uint32_t*>(pB + n * KSTRB + kb);
                Bf[1] = *reinterpret_cast<uint32_t*>(pB + n * KSTRB + kb + 16);
                #pragma unroll
                for (int mt = 0; mt < 2; mt++)
                    mma_bf16(acc[mt][nt], Af[mt], Bf);
            }
        }
    }

    #pragma unroll
    for (int mt = 0; mt < 2; mt++) {
        const int row0 = bm + wm + mt * 16 + g;
        #pragma unroll
        for (int nt = 0; nt < 8; nt++) {
            const int col = bn + wn + nt * 8 + tg * 2;
            float2 b2 = *reinterpret_cast<const float2*>(&bias[col]);
            float v00 = acc[mt][nt][0] + b2.x, v01 = acc[mt][nt][1] + b2.y;
            float v10 = acc[mt][nt][2] + b2.x, v11 = acc[mt][nt][3] + b2.y;
            if (SPLIT) {
                uint32_t h0, l0, h1, l1;
                bf16_split(v00, v01, h0, l0);
                bf16_split(v10, v11, h1, l1);
                *reinterpret_cast<uint32_t*>(&C2[row0 * 1024 + col]) = h0;
                *reinterpret_cast<uint32_t*>(&C2[row0 * 1024 + 512 + col]) = l0;
                *reinterpret_cast<uint32_t*>(&C2[(row0 + 8) * 1024 + col]) = h1;
                *reinterpret_cast<uint32_t*>(&C2[(row0 + 8) * 1024 + 512 + col]) = l1;
            } else {
                *reinterpret_cast<float2*>(&C[row0 * DM_ + col]) = make_float2(v00, v01);
                *reinterpret_cast<float2*>(&C[(row0 + 8) * DM_ + col]) = make_float2(v10, v11);
            }
        }
    }
}

__global__ __launch_bounds__(256, 2) void qkv_gemm_tc_b()
{
    __nv_bfloat16* C2 = (blockIdx.z == 0) ? g_Q2
                      : (blockIdx.z == 1) ? g_K2 : g_V2;
    gemm_bf16_body<true>(g_x2, g_W2 + blockIdx.z * DM_ * 1024,
                         g_bqkv + blockIdx.z * DM_,
                         nullptr, C2, blockIdx.y * 128, blockIdx.x * 128);
}

__global__ __launch_bounds__(256, 2) void out_gemm_tc(
    const float* __restrict__ bo, float* __restrict__ out)
{
    gemm_bf16_body<false>(g_ctx2, g_W2 + 3 * DM_ * 1024, bo, out, nullptr,
                          blockIdx.y * 128, blockIdx.x * 128);
}

// ===========================================================================
// vmean: two-stage parallel reduction over bf16 V2 (hi+lo)
// ===========================================================================
__global__ __launch_bounds__(256) void vmean1()
{
    __shared__ float red[4][64];
    const int bh = blockIdx.x, ch = blockIdx.y;
    const int b = bh >> 3, h = bh & 7;
    const int d = threadIdx.x & 63, rg = threadIdx.x >> 6;
    const int base = ch * 256 + rg * 64;
    float s = 0.f;
    #pragma unroll 4
    for (int i = 0; i < 64; i++) {
        const __nv_bfloat16* p = g_V2 + (size_t)(b * S_ + base + i) * 1024 + h * 64 + d;
        s += __bfloat162float(p[0]) + __bfloat162float(p[512]);
    }
    red[rg][d] = s;
    __syncthreads();
    if (rg == 0)
        g_vpart[(bh * 8 + ch) * 64 + d] = red[0][d] + red[1][d] + red[2][d] + red[3][d];
}
__global__ void vmean2()
{
    const int bh = blockIdx.x, d = threadIdx.x;
    float s = 0.f;
    #pragma unroll
    for (int c = 0; c < 8; c++) s += g_vpart[(bh * 8 + c) * 64 + d];
    g_vmean[bh * 64 + d] = s * (1.0f / S_);
}

// ===========================================================================
// Banded attention on mma.sync (bf16x3 split)
// ===========================================================================
#define QROW 272
#define SQ2_OFF 0
#define SKV_OFF 17408
#define SS_OFF 34816
#define SS_STRB 1296
#define ATTN_SMEM_BYTES (SS_OFF + 64 * SS_STRB)   // 117760

__global__ __launch_bounds__(256, 1) void attn_kernel(const int* __restrict__ x_len)
{
    extern __shared__ char sm[];
    const int q0 = blockIdx.x * 64;
    const int h  = blockIdx.y;
    const int b  = blockIdx.z;
    const int tid = threadIdx.x;
    const int wid = tid >> 5, lane = tid & 31;
    const int g = lane >> 2, tg = lane & 3;
    const int wm = (wid & 3) * 16, wn2 = (wid >> 2) * 32;
    const int xlen = x_len[b];
    __shared__ int sEmpty[64];

    const int j_lo = max(0, q0 - LEFT_);
    const int j_hi = min(S_ - 1, q0 + 63 + RIGHT_);
    const int KT = j_hi - j_lo + 1;        // multiple of 64
    const int NC = KT >> 6;

    // ---- Load Q2 tile (hi|lo) ----
    #pragma unroll
    for (int l = 0; l < 4; l++) {
        int i = tid + l * 256;
        int row = i >> 4, seg = i & 15;
        const __nv_bfloat16* src = g_Q2 + (size_t)(b * S_ + q0 + row) * 1024
            + ((seg < 8) ? (h * 64 + seg * 8) : (512 + h * 64 + (seg - 8) * 8));
        *reinterpret_cast<uint4*>(sm + SQ2_OFF + row * QROW + seg * 16) =
            *reinterpret_cast<const uint4*>(src);
    }

    // ---- Scores: per 64-key chunk, QK^T via 3-region MMA ----
    for (int c = 0; c < NC; c++) {
        __syncthreads();
        #pragma unroll
        for (int l = 0; l < 4; l++) {
            int i = tid + l * 256;
            int row = i >> 4, seg = i & 15;
            const __nv_bfloat16* src = g_K2 + (size_t)(b * S_ + j_lo + c * 64 + row) * 1024
                + ((seg < 8) ? (h * 64 + seg * 8) : (512 + h * 64 + (seg - 8) * 8));
            *reinterpret_cast<uint4*>(sm + SKV_OFF + row * QROW + seg * 16) =
                *reinterpret_cast<const uint4*>(src);
        }
        __syncthreads();

        float cs[4][4] = {};
        #pragma unroll
        for (int r3 = 0; r3 < 3; r3++) {
            const int ao = (r3 == 2) ? 128 : 0;
            const int bo = (r3 == 1) ? 128 : 0;
            #pragma unroll
            for (int ks = 0; ks < 4; ks++) {
                uint32_t A[4];
                const char* ab = sm + SQ2_OFF + (wm + g) * QROW + ao + ks * 32 + tg * 4;
                A[0] = *reinterpret_cast<const uint32_t*>(ab);
                A[1] = *reinterpret_cast<const uint32_t*>(ab + 8 * QROW);
                A[2] = *reinterpret_cast<const uint32_t*>(ab + 16);
                A[3] = *reinterpret_cast<const uint32_t*>(ab + 8 * QROW + 16);
                #pragma unroll
                for (int nt = 0; nt < 4; nt++) {
                    const char* bb = sm + SKV_OFF + (wn2 + nt * 8 + g) * QROW + bo
                                     + ks * 32 + tg * 4;
                    uint32_t Bf[2];
                    Bf[0] = *reinterpret_cast<const uint32_t*>(bb);
                    Bf[1] = *reinterpret_cast<const uint32_t*>(bb + 16);
                    mma_bf16(cs[nt], A, Bf);
                }
            }
        }
        #pragma unroll
        for (int nt = 0; nt < 4; nt++) {
            int colb = (c * 64 + wn2 + nt * 8 + tg * 2) * 4;
            *reinterpret_cast<float2*>(sm + SS_OFF + (wm + g) * SS_STRB + colb) =
                make_float2(cs[nt][0] * 0.125f, cs[nt][1] * 0.125f);
            *reinterpret_cast<float2*>(sm + SS_OFF + (wm + g + 8) * SS_STRB + colb) =
                make_float2(cs[nt][2] * 0.125f, cs[nt][3] * 0.125f);
        }
    }
    __syncthreads();

    // ---- Softmax (fp32) + in-place conversion to P hi/lo bf16 ----
    for (int r = wid; r < 64; r += 8) {
        const int iq = q0 + r;
        const int lo = max(0, iq - LEFT_);
        const int hi = min(S_ - 1, iq + RIGHT_);
        const int vh = min(hi, xlen - 1);
        const int llo = lo - j_lo, lhi = vh - j_lo;
        char* rowb = sm + SS_OFF + r * SS_STRB;
        const float* rowf = reinterpret_cast<const float*>(rowb);
        if (lane == 0) sEmpty[r] = (lhi < llo);

        float ev[10];
        float mx = -3.4e38f;
        #pragma unroll
        for (int i = 0; i < 10; i++) {
            int k = lane + i * 32;
            bool in = (k >= llo && k <= lhi);
            float v = in ? rowf[k] : -3.4e38f;
            ev[i] = v;
            mx = fmaxf(mx, v);
        }
        #pragma unroll
        for (int o = 16; o; o >>= 1) mx = fmaxf(mx, __shfl_xor_sync(~0u, mx, o));
        float sum = 0.f;
        #pragma unroll
        for (int i = 0; i < 10; i++) {
            float e = (ev[i] > -1e37f) ? __expf(ev[i] - mx) : 0.f;
            ev[i] = e; sum += e;
        }
        #pragma unroll
        for (int o = 16; o; o >>= 1) sum += __shfl_xor_sync(~0u, sum, o);
        float inv = (sum > 0.f) ? (1.0f / sum) : 0.f;
        __syncwarp();
        #pragma unroll
        for (int i = 0; i < 10; i++) {
            int k = lane + i * 32;
            if (k < KT) {
                float p = ev[i] * inv;
                __nv_bfloat16 ph = __float2bfloat16_rn(p);
                __nv_bfloat16 pl = __float2bfloat16_rn(p - __bfloat162float(ph));
                *reinterpret_cast<__nv_bfloat16*>(rowb + 2 * k) = ph;
                *reinterpret_cast<__nv_bfloat16*>(rowb + 640 + 2 * k) = pl;
            }
        }
    }
    __syncthreads();

    // ---- ctx = P @ V (3-region MMA, V transposed per chunk) ----
    float co[4][4] = {};
    for (int c = 0; c < NC; c++) {
        __syncthreads();
        // Load V chunk transposed: VT[d][ jh(64 bf16) | jl(64 bf16) ]
        #pragma unroll
        for (int l = 0; l < 4; l++) {
            int j = (tid >> 4) + l * 16;
            int dq = (tid & 15) * 4;
            const __nv_bfloat16* src = g_V2 + (size_t)(b * S_ + j_lo + c * 64 + j) * 1024
                                       + h * 64 + dq;
            uint2 hv = *reinterpret_cast<const uint2*>(src);
            uint2 lv = *reinterpret_cast<const uint2*>(src + 512);
            const __nv_bfloat16* hb = reinterpret_cast<const __nv_bfloat16*>(&hv);
            const __nv_bfloat16* lb = reinterpret_cast<const __nv_bfloat16*>(&lv);
            #pragma unroll
            for (int q = 0; q < 4; q++) {
                *reinterpret_cast<__nv_bfloat16*>(sm + SKV_OFF + (dq + q) * QROW + 2 * j) = hb[q];
                *reinterpret_cast<__nv_bfloat16*>(sm + SKV_OFF + (dq + q) * QROW + 128 + 2 * j) = lb[q];
            }
        }
        __syncthreads();

        #pragma unroll
        for (int r3 = 0; r3 < 3; r3++) {
            const int ao = (r3 == 2) ? 640 : 0;   // P lo region
            const int bo = (r3 == 1) ? 128 : 0;   // V lo region
            #pragma unroll
            for (int ks = 0; ks < 4; ks++) {
                uint32_t A[4];
                const char* ab = sm + SS_OFF + (wm + g) * SS_STRB + ao + c * 128
                                 + ks * 32 + tg * 4;
                A[0] = *reinterpret_cast<const uint32_t*>(ab);
                A[1] = *reinterpret_cast<const uint32_t*>(ab + 8 * SS_STRB);
                A[2] = *reinterpret_cast<const uint32_t*>(ab + 16);
                A[3] = *reinterpret_cast<const uint32_t*>(ab + 8 * SS_STRB + 16);
                #pragma unroll
                for (int nt = 0; nt < 4; nt++) {
                    const char* bb = sm + SKV_OFF + (wn2 + nt * 8 + g) * QROW + bo
                                     + ks * 32 + tg * 4;
                    uint32_t Bf[2];
                    Bf[0] = *reinterpret_cast<const uint32_t*>(bb);
                    Bf[1] = *reinterpret_cast<const uint32_t*>(bb + 16);
                    mma_bf16(co[nt], A, Bf);
                }
            }
        }
    }
    __syncthreads();

    // ---- Epilogue: split-write ctx2; empty rows get vmean ----
    #pragma unroll
    for (int nt = 0; nt < 4; nt++) {
        const int dcol = wn2 + nt * 8 + tg * 2;
        #pragma unroll
        for (int half = 0; half < 2; half++) {
            const int r = wm + g + half * 8;
            float v0 = co[nt][half * 2 + 0];
            float v1 = co[nt][half * 2 + 1];
            if (sEmpty[r]) {
                v0 += g_vmean[(b * H_ + h) * 64 + dcol];
                v1 += g_vmean[(b * H_ + h) * 64 + dcol + 1];
            }
            uint32_t hh, ll;
            bf16_split(v0, v1, hh, ll);
            __nv_bfloat16* dst = g_ctx2 + (size_t)(b * S_ + q0 + r) * 1024 + h * 64 + dcol;
            *reinterpret_cast<uint32_t*>(dst) = hh;
            *reinterpret_cast<uint32_t*>(dst + 512) = ll;
        }
    }
}

// ---------------------------------------------------------------------------
extern "C" void kernel_launch(void* const* d_in, const int* in_sizes, int n_in,
                              void* d_out, int out_size)
{
    const float* x  = (const float*)d_in[0];
    const float* Wq = (const float*)d_in[1];
    const float* bq = (const float*)d_in[2];
    const float* Wk = (const float*)d_in[3];
    const float* bk = (const float*)d_in[4];
    const float* Wv = (const float*)d_in[5];
    const float* bv = (const float*)d_in[6];
    const float* Wo = (const float*)d_in[7];
    const float* bo = (const float*)d_in[8];
    const int* xlen = (const int*)d_in[9];
    float* out = (float*)d_out;

    void* px2;
    cudaGetSymbolAddress(&px2, g_x2);

    cudaFuncSetAttribute(qkv_gemm_tc_b,
                         cudaFuncAttributeMaxDynamicSharedMemorySize,
                         GEMM_SMEM_BYTES);
    cudaFuncSetAttribute(out_gemm_tc,
                         cudaFuncAttributeMaxDynamicSharedMemorySize,
                         GEMM_SMEM_BYTES);
    cudaFuncSetAttribute(attn_kernel,
                         cudaFuncAttributeMaxDynamicSharedMemorySize,
                         ATTN_SMEM_BYTES);

    split_a<<<M_ * DM_ / 1024, 256>>>(x, (__nv_bfloat16*)px2);
    split_w<<<dim3(16, 16, 4), 256>>>(Wq, Wk, Wv, Wo);
    stage_bias<<<2, 256>>>(bq, bk, bv);

    qkv_gemm_tc_b<<<dim3(DM_ / 128, M_ / 128, 3), 256, GEMM_SMEM_BYTES>>>();

    vmean1<<<dim3(B_ * H_, 8), 256>>>();
    vmean2<<<B_ * H_, 64>>>();

    attn_kernel<<<dim3(S_ / 64, H_, B_), 256, ATTN_SMEM_BYTES>>>(xlen);

    out_gemm_tc<<<dim3(DM_ / 128, M_ / 128), 256, GEMM_SMEM_BYTES>>>(bo, out);
}

// round 15
// speedup vs baseline: 1.2895x; 1.1667x over previous
#include <cuda_runtime.h>
#include <cuda_bf16.h>
#include <cstdint>
#include <math.h>

#define B_ 4
#define S_ 2048
#define DM_ 512
#define H_ 8
#define D_ 64
#define LEFT_ 128
#define RIGHT_ 128
#define M_ (B_ * S_)

// Scratch (device globals: allocation-free rule)
// Split bf16 layout: [row][ hi(512) | lo(512) ]
__device__ __nv_bfloat16 g_x2[M_ * 1024];
__device__ __nv_bfloat16 g_Q2[M_ * 1024];
__device__ __nv_bfloat16 g_K2[M_ * 1024];
__device__ __nv_bfloat16 g_V2[M_ * 1024];
__device__ __nv_bfloat16 g_ctx2[M_ * 1024];
__device__ __nv_bfloat16 g_W2[4 * DM_ * 1024];   // [w][n][ hi(k) | lo(k) ]
__device__ float g_vmean[B_ * H_ * D_];
__device__ float g_vpart[B_ * H_ * 8 * 64];
__device__ float g_bqkv[3 * DM_];

__device__ __forceinline__ uint32_t smem_u32(const void* p) {
    uint32_t a;
    asm("{ .reg .u64 t; cvta.to.shared.u64 t, %1; cvt.u32.u64 %0, t; }"
        : "=r"(a) : "l"(p));
    return a;
}
__device__ __forceinline__ void cp16(uint32_t s, const void* g) {
    asm volatile("cp.async.cg.shared.global [%0], [%1], 16;"
                 :: "r"(s), "l"(g) : "memory");
}
#define CP_COMMIT() asm volatile("cp.async.commit_group;" ::: "memory")
#define CP_WAIT(n)  asm volatile("cp.async.wait_group %0;" :: "n"(n) : "memory")

__device__ __forceinline__ void ldsm_x4(uint32_t* r, uint32_t addr) {
    asm volatile("ldmatrix.sync.aligned.m8n8.x4.shared.b16 {%0,%1,%2,%3}, [%4];"
                 : "=r"(r[0]), "=r"(r[1]), "=r"(r[2]), "=r"(r[3]) : "r"(addr));
}

__device__ __forceinline__ void bf16_split(float x0, float x1,
                                           uint32_t& hi, uint32_t& lo) {
    __nv_bfloat162 h = __float22bfloat162_rn(make_float2(x0, x1));
    float2 f = __bfloat1622float2(h);
    __nv_bfloat162 l = __float22bfloat162_rn(make_float2(x0 - f.x, x1 - f.y));
    hi = *reinterpret_cast<uint32_t*>(&h);
    lo = *reinterpret_cast<uint32_t*>(&l);
}

__device__ __forceinline__ void mma_bf16(float* c, const uint32_t* a,
                                         const uint32_t* b) {
    asm volatile(
        "mma.sync.aligned.m16n8k16.row.col.f32.bf16.bf16.f32 "
        "{%0,%1,%2,%3}, {%4,%5,%6,%7}, {%8,%9}, {%0,%1,%2,%3};"
        : "+f"(c[0]), "+f"(c[1]), "+f"(c[2]), "+f"(c[3])
        : "r"(a[0]), "r"(a[1]), "r"(a[2]), "r"(a[3]), "r"(b[0]), "r"(b[1]));
}

// ===========================================================================
// Split kernels
// ===========================================================================
__global__ __launch_bounds__(256) void split_a(const float* __restrict__ src,
                                               __nv_bfloat16* __restrict__ dst)
{
    int idx = (blockIdx.x * 256 + threadIdx.x) * 4;
    int row = idx >> 9, k = idx & 511;
    float4 v = *reinterpret_cast<const float4*>(&src[idx]);
    uint32_t h0, l0, h1, l1;
    bf16_split(v.x, v.y, h0, l0);
    bf16_split(v.z, v.w, h1, l1);
    *reinterpret_cast<uint2*>(&dst[row * 1024 + k]) = make_uint2(h0, h1);
    *reinterpret_cast<uint2*>(&dst[row * 1024 + 512 + k]) = make_uint2(l0, l1);
}

__global__ __launch_bounds__(256) void split_w(
    const float* __restrict__ W0, const float* __restrict__ W1,
    const float* __restrict__ W2p, const float* __restrict__ W3)
{
    __shared__ float t[32][33];
    const float* W = (blockIdx.z == 0) ? W0 : (blockIdx.z == 1) ? W1
                   : (blockIdx.z == 2) ? W2p : W3;
    __nv_bfloat16* dst = g_W2 + blockIdx.z * DM_ * 1024;
    int bx = blockIdx.x * 32;
    int by = blockIdx.y * 32;
    int tx = threadIdx.x & 31, ty = threadIdx.x >> 5;
    #pragma unroll
    for (int i = 0; i < 4; i++)
        t[ty + i * 8][tx] = W[(bx + ty + i * 8) * DM_ + by + tx];
    __syncthreads();
    #pragma unroll
    for (int i = 0; i < 4; i++) {
        int n = by + ty + i * 8;
        int k = bx + tx;
        float v = t[tx][ty + i * 8];
        __nv_bfloat16 h = __float2bfloat16_rn(v);
        __nv_bfloat16 l = __float2bfloat16_rn(v - __bfloat162float(h));
        dst[n * 1024 + k] = h;
        dst[n * 1024 + 512 + k] = l;
    }
}

__global__ void stage_bias(const float* bq, const float* bk, const float* bv)
{
    int i = threadIdx.x + blockIdx.x * 256;
    if (i < DM_) { g_bqkv[i] = bq[i]; g_bqkv[DM_ + i] = bk[i]; g_bqkv[2 * DM_ + i] = bv[i]; }
}

// ===========================================================================
// bf16x3 GEMM with fragment reuse + ldmatrix. Physical K=512, BK=32,
// 2-stage cp.async. Stage holds Ah|Al|Bh|Bl (each 128 rows x 32 bf16,
// row stride 80 B -> conflict-free LDSM phases). 3 MMAs per fragment set.
// ===========================================================================
#define RSTR 80
#define REG_SZ 10240                 // one region: 128 * 80
#define STG2 40960                   // 4 regions
#define GEMM_SMEM_BYTES (2 * STG2)   // 81920
#define NCHUNK2 16

__device__ __forceinline__ void issue_chunk2(
    uint32_t sbase, const __nv_bfloat16* __restrict__ A2,
    const __nv_bfloat16* __restrict__ Bt,
    int bm, int bn, int c, int stage, int tid)
{
    const int row = tid >> 1, h = tid & 1;
    const int k0 = c * 32;
    const __nv_bfloat16* ga = &A2[(size_t)(bm + row) * 1024 + k0 + h * 16];
    const __nv_bfloat16* gb = &Bt[(size_t)(bn + row) * 1024 + k0 + h * 16];
    uint32_t s = sbase + stage * STG2 + row * RSTR + h * 32;
    cp16(s, ga);                 cp16(s + 16, ga + 8);           // A hi
    cp16(s + REG_SZ, ga + 512);  cp16(s + REG_SZ + 16, ga + 520); // A lo
    cp16(s + 2 * REG_SZ, gb);    cp16(s + 2 * REG_SZ + 16, gb + 8);     // B hi
    cp16(s + 3 * REG_SZ, gb + 512); cp16(s + 3 * REG_SZ + 16, gb + 520); // B lo
}

template <bool SPLIT>
__device__ __forceinline__ void gemm_bf16_body(
    const __nv_bfloat16* __restrict__ A2, const __nv_bfloat16* __restrict__ Bt,
    const float* __restrict__ bias, float* __restrict__ C,
    __nv_bfloat16* __restrict__ C2, int bm, int bn)
{
    extern __shared__ char smc[];
    const uint32_t sbase = smem_u32(smc);
    const int tid = threadIdx.x;
    const int wid = tid >> 5, lane = tid & 31;
    const int g = lane >> 2, tg = lane & 3;
    const int wm = (wid & 3) * 32, wn = (wid >> 2) * 64;

    // ldmatrix per-lane address offsets
    const int aoff = (lane & 15) * RSTR + (lane >> 4) * 16;
    const int boff = ((lane & 7) + ((lane >> 4) << 3)) * RSTR + ((lane >> 3) & 1) * 16;

    issue_chunk2(sbase, A2, Bt, bm, bn, 0, 0, tid);
    CP_COMMIT();

    float acc[2][8][4] = {};

    for (int c = 0; c < NCHUNK2; c++) {
        if (c + 1 < NCHUNK2) {
            issue_chunk2(sbase, A2, Bt, bm, bn, c + 1, (c + 1) & 1, tid);
            CP_COMMIT();
            CP_WAIT(1);
        } else {
            CP_WAIT(0);
        }
        __syncthreads();

        const uint32_t sb = sbase + (c & 1) * STG2;
        const uint32_t aAh = sb + wm * RSTR + aoff;
        const uint32_t aAl = aAh + REG_SZ;
        const uint32_t aBh = sb + 2 * REG_SZ + wn * RSTR + boff;
        const uint32_t aBl = aBh + REG_SZ;

        #pragma unroll
        for (int ks = 0; ks < 2; ks++) {
            uint32_t Ah[2][4], Al[2][4];
            ldsm_x4(Ah[0], aAh + ks * 32);
            ldsm_x4(Ah[1], aAh + 1280 + ks * 32);
            ldsm_x4(Al[0], aAl + ks * 32);
            ldsm_x4(Al[1], aAl + 1280 + ks * 32);
            #pragma unroll
            for (int ntp = 0; ntp < 4; ntp++) {
                uint32_t Bh4[4], Bl4[4];
                ldsm_x4(Bh4, aBh + ntp * 1280 + ks * 32);
                ldsm_x4(Bl4, aBl + ntp * 1280 + ks * 32);
                #pragma unroll
                for (int mt = 0; mt < 2; mt++) {
                    mma_bf16(acc[mt][2 * ntp],     Ah[mt], Bh4);
                    mma_bf16(acc[mt][2 * ntp],     Ah[mt], Bl4);
                    mma_bf16(acc[mt][2 * ntp],     Al[mt], Bh4);
                    mma_bf16(acc[mt][2 * ntp + 1], Ah[mt], Bh4 + 2);
                    mma_bf16(acc[mt][2 * ntp + 1], Ah[mt], Bl4 + 2);
                    mma_bf16(acc[mt][2 * ntp + 1], Al[mt], Bh4 + 2);
                }
            }
        }
        __syncthreads();
    }

    #pragma unroll
    for (int mt = 0; mt < 2; mt++) {
        const int row0 = bm + wm + mt * 16 + g;
        #pragma unroll
        for (int nt = 0; nt < 8; nt++) {
            const int col = bn + wn + nt * 8 + tg * 2;
            float2 b2 = *reinterpret_cast<const float2*>(&bias[col]);
            float v00 = acc[mt][nt][0] + b2.x, v01 = acc[mt][nt][1] + b2.y;
            float v10 = acc[mt][nt][2] + b2.x, v11 = acc[mt][nt][3] + b2.y;
            if (SPLIT) {
                uint32_t h0, l0, h1, l1;
                bf16_split(v00, v01, h0, l0);
                bf16_split(v10, v11, h1, l1);
                *reinterpret_cast<uint32_t*>(&C2[(size_t)row0 * 1024 + col]) = h0;
                *reinterpret_cast<uint32_t*>(&C2[(size_t)row0 * 1024 + 512 + col]) = l0;
                *reinterpret_cast<uint32_t*>(&C2[(size_t)(row0 + 8) * 1024 + col]) = h1;
                *reinterpret_cast<uint32_t*>(&C2[(size_t)(row0 + 8) * 1024 + 512 + col]) = l1;
            } else {
                *reinterpret_cast<float2*>(&C[(size_t)row0 * DM_ + col]) = make_float2(v00, v01);
                *reinterpret_cast<float2*>(&C[(size_t)(row0 + 8) * DM_ + col]) = make_float2(v10, v11);
            }
        }
    }
}

__global__ __launch_bounds__(256, 2) void qkv_gemm_tc_b()
{
    __nv_bfloat16* C2 = (blockIdx.z == 0) ? g_Q2
                      : (blockIdx.z == 1) ? g_K2 : g_V2;
    gemm_bf16_body<true>(g_x2, g_W2 + blockIdx.z * DM_ * 1024,
                         g_bqkv + blockIdx.z * DM_,
                         nullptr, C2, blockIdx.y * 128, blockIdx.x * 128);
}

__global__ __launch_bounds__(256, 2) void out_gemm_tc(
    const float* __restrict__ bo, float* __restrict__ out)
{
    gemm_bf16_body<false>(g_ctx2, g_W2 + 3 * DM_ * 1024, bo, out, nullptr,
                          blockIdx.y * 128, blockIdx.x * 128);
}

// ===========================================================================
// vmean: two-stage parallel reduction over bf16 V2 (hi+lo)
// ===========================================================================
__global__ __launch_bounds__(256) void vmean1()
{
    __shared__ float red[4][64];
    const int bh = blockIdx.x, ch = blockIdx.y;
    const int b = bh >> 3, h = bh & 7;
    const int d = threadIdx.x & 63, rg = threadIdx.x >> 6;
    const int base = ch * 256 + rg * 64;
    float s = 0.f;
    #pragma unroll 4
    for (int i = 0; i < 64; i++) {
        const __nv_bfloat16* p = g_V2 + (size_t)(b * S_ + base + i) * 1024 + h * 64 + d;
        s += __bfloat162float(p[0]) + __bfloat162float(p[512]);
    }
    red[rg][d] = s;
    __syncthreads();
    if (rg == 0)
        g_vpart[(bh * 8 + ch) * 64 + d] = red[0][d] + red[1][d] + red[2][d] + red[3][d];
}
__global__ void vmean2()
{
    const int bh = blockIdx.x, d = threadIdx.x;
    float s = 0.f;
    #pragma unroll
    for (int c = 0; c < 8; c++) s += g_vpart[(bh * 8 + c) * 64 + d];
    g_vmean[bh * 64 + d] = s * (1.0f / S_);
}

// ===========================================================================
// Banded attention on mma.sync (bf16x3 split) — unchanged from R10
// ===========================================================================
#define QROW 272
#define SQ2_OFF 0
#define SKV_OFF 17408
#define SS_OFF 34816
#define SS_STRB 1296
#define ATTN_SMEM_BYTES (SS_OFF + 64 * SS_STRB)   // 117760

__global__ __launch_bounds__(256, 1) void attn_kernel(const int* __restrict__ x_len)
{
    extern __shared__ char sm[];
    const int q0 = blockIdx.x * 64;
    const int h  = blockIdx.y;
    const int b  = blockIdx.z;
    const int tid = threadIdx.x;
    const int wid = tid >> 5, lane = tid & 31;
    const int g = lane >> 2, tg = lane & 3;
    const int wm = (wid & 3) * 16, wn2 = (wid >> 2) * 32;
    const int xlen = x_len[b];
    __shared__ int sEmpty[64];

    const int j_lo = max(0, q0 - LEFT_);
    const int j_hi = min(S_ - 1, q0 + 63 + RIGHT_);
    const int KT = j_hi - j_lo + 1;        // multiple of 64
    const int NC = KT >> 6;

    // ---- Load Q2 tile (hi|lo) ----
    #pragma unroll
    for (int l = 0; l < 4; l++) {
        int i = tid + l * 256;
        int row = i >> 4, seg = i & 15;
        const __nv_bfloat16* src = g_Q2 + (size_t)(b * S_ + q0 + row) * 1024
            + ((seg < 8) ? (h * 64 + seg * 8) : (512 + h * 64 + (seg - 8) * 8));
        *reinterpret_cast<uint4*>(sm + SQ2_OFF + row * QROW + seg * 16) =
            *reinterpret_cast<const uint4*>(src);
    }

    // ---- Scores: per 64-key chunk, QK^T via 3-region MMA ----
    for (int c = 0; c < NC; c++) {
        __syncthreads();
        #pragma unroll
        for (int l = 0; l < 4; l++) {
            int i = tid + l * 256;
            int row = i >> 4, seg = i & 15;
            const __nv_bfloat16* src = g_K2 + (size_t)(b * S_ + j_lo + c * 64 + row) * 1024
                + ((seg < 8) ? (h * 64 + seg * 8) : (512 + h * 64 + (seg - 8) * 8));
            *reinterpret_cast<uint4*>(sm + SKV_OFF + row * QROW + seg * 16) =
                *reinterpret_cast<const uint4*>(src);
        }
        __syncthreads();

        float cs[4][4] = {};
        #pragma unroll
        for (int r3 = 0; r3 < 3; r3++) {
            const int ao = (r3 == 2) ? 128 : 0;
            const int bo = (r3 == 1) ? 128 : 0;
            #pragma unroll
            for (int ks = 0; ks < 4; ks++) {
                uint32_t A[4];
                const char* ab = sm + SQ2_OFF + (wm + g) * QROW + ao + ks * 32 + tg * 4;
                A[0] = *reinterpret_cast<const uint32_t*>(ab);
                A[1] = *reinterpret_cast<const uint32_t*>(ab + 8 * QROW);
                A[2] = *reinterpret_cast<const uint32_t*>(ab + 16);
                A[3] = *reinterpret_cast<const uint32_t*>(ab + 8 * QROW + 16);
                #pragma unroll
                for (int nt = 0; nt < 4; nt++) {
                    const char* bb = sm + SKV_OFF + (wn2 + nt * 8 + g) * QROW + bo
                                     + ks * 32 + tg * 4;
                    uint32_t Bf[2];
                    Bf[0] = *reinterpret_cast<const uint32_t*>(bb);
                    Bf[1] = *reinterpret_cast<const uint32_t*>(bb + 16);
                    mma_bf16(cs[nt], A, Bf);
                }
            }
        }
        #pragma unroll
        for (int nt = 0; nt < 4; nt++) {
            int colb = (c * 64 + wn2 + nt * 8 + tg * 2) * 4;
            *reinterpret_cast<float2*>(sm + SS_OFF + (wm + g) * SS_STRB + colb) =
                make_float2(cs[nt][0] * 0.125f, cs[nt][1] * 0.125f);
            *reinterpret_cast<float2*>(sm + SS_OFF + (wm + g + 8) * SS_STRB + colb) =
                make_float2(cs[nt][2] * 0.125f, cs[nt][3] * 0.125f);
        }
    }
    __syncthreads();

    // ---- Softmax (fp32) + in-place conversion to P hi/lo bf16 ----
    for (int r = wid; r < 64; r += 8) {
        const int iq = q0 + r;
        const int lo = max(0, iq - LEFT_);
        const int hi = min(S_ - 1, iq + RIGHT_);
        const int vh = min(hi, xlen - 1);
        const int llo = lo - j_lo, lhi = vh - j_lo;
        char* rowb = sm + SS_OFF + r * SS_STRB;
        const float* rowf = reinterpret_cast<const float*>(rowb);
        if (lane == 0) sEmpty[r] = (lhi < llo);

        float ev[10];
        float mx = -3.4e38f;
        #pragma unroll
        for (int i = 0; i < 10; i++) {
            int k = lane + i * 32;
            bool in = (k >= llo && k <= lhi);
            float v = in ? rowf[k] : -3.4e38f;
            ev[i] = v;
            mx = fmaxf(mx, v);
        }
        #pragma unroll
        for (int o = 16; o; o >>= 1) mx = fmaxf(mx, __shfl_xor_sync(~0u, mx, o));
        float sum = 0.f;
        #pragma unroll
        for (int i = 0; i < 10; i++) {
            float e = (ev[i] > -1e37f) ? __expf(ev[i] - mx) : 0.f;
            ev[i] = e; sum += e;
        }
        #pragma unroll
        for (int o = 16; o; o >>= 1) sum += __shfl_xor_sync(~0u, sum, o);
        float inv = (sum > 0.f) ? (1.0f / sum) : 0.f;
        __syncwarp();
        #pragma unroll
        for (int i = 0; i < 10; i++) {
            int k = lane + i * 32;
            if (k < KT) {
                float p = ev[i] * inv;
                __nv_bfloat16 ph = __float2bfloat16_rn(p);
                __nv_bfloat16 pl = __float2bfloat16_rn(p - __bfloat162float(ph));
                *reinterpret_cast<__nv_bfloat16*>(rowb + 2 * k) = ph;
                *reinterpret_cast<__nv_bfloat16*>(rowb + 640 + 2 * k) = pl;
            }
        }
    }
    __syncthreads();

    // ---- ctx = P @ V (3-region MMA, V transposed per chunk) ----
    float co[4][4] = {};
    for (int c = 0; c < NC; c++) {
        __syncthreads();
        // Load V chunk transposed: VT[d][ jh(64 bf16) | jl(64 bf16) ]
        #pragma unroll
        for (int l = 0; l < 4; l++) {
            int j = (tid >> 4) + l * 16;
            int dq = (tid & 15) * 4;
            const __nv_bfloat16* src = g_V2 + (size_t)(b * S_ + j_lo + c * 64 + j) * 1024
                                       + h * 64 + dq;
            uint2 hv = *reinterpret_cast<const uint2*>(src);
            uint2 lv = *reinterpret_cast<const uint2*>(src + 512);
            const __nv_bfloat16* hb = reinterpret_cast<const __nv_bfloat16*>(&hv);
            const __nv_bfloat16* lb = reinterpret_cast<const __nv_bfloat16*>(&lv);
            #pragma unroll
            for (int q = 0; q < 4; q++) {
                *reinterpret_cast<__nv_bfloat16*>(sm + SKV_OFF + (dq + q) * QROW + 2 * j) = hb[q];
                *reinterpret_cast<__nv_bfloat16*>(sm + SKV_OFF + (dq + q) * QROW + 128 + 2 * j) = lb[q];
            }
        }
        __syncthreads();

        #pragma unroll
        for (int r3 = 0; r3 < 3; r3++) {
            const int ao = (r3 == 2) ? 640 : 0;   // P lo region
            const int bo = (r3 == 1) ? 128 : 0;   // V lo region
            #pragma unroll
            for (int ks = 0; ks < 4; ks++) {
                uint32_t A[4];
                const char* ab = sm + SS_OFF + (wm + g) * SS_STRB + ao + c * 128
                                 + ks * 32 + tg * 4;
                A[0] = *reinterpret_cast<const uint32_t*>(ab);
                A[1] = *reinterpret_cast<const uint32_t*>(ab + 8 * SS_STRB);
                A[2] = *reinterpret_cast<const uint32_t*>(ab + 16);
                A[3] = *reinterpret_cast<const uint32_t*>(ab + 8 * SS_STRB + 16);
                #pragma unroll
                for (int nt = 0; nt < 4; nt++) {
                    const char* bb = sm + SKV_OFF + (wn2 + nt * 8 + g) * QROW + bo
                                     + ks * 32 + tg * 4;
                    uint32_t Bf[2];
                    Bf[0] = *reinterpret_cast<const uint32_t*>(bb);
                    Bf[1] = *reinterpret_cast<const uint32_t*>(bb + 16);
                    mma_bf16(co[nt], A, Bf);
                }
            }
        }
    }
    __syncthreads();

    // ---- Epilogue: split-write ctx2; empty rows get vmean ----
    #pragma unroll
    for (int nt = 0; nt < 4; nt++) {
        const int dcol = wn2 + nt * 8 + tg * 2;
        #pragma unroll
        for (int half = 0; half < 2; half++) {
            const int r = wm + g + half * 8;
            float v0 = co[nt][half * 2 + 0];
            float v1 = co[nt][half * 2 + 1];
            if (sEmpty[r]) {
                v0 += g_vmean[(b * H_ + h) * 64 + dcol];
                v1 += g_vmean[(b * H_ + h) * 64 + dcol + 1];
            }
            uint32_t hh, ll;
            bf16_split(v0, v1, hh, ll);
            __nv_bfloat16* dst = g_ctx2 + (size_t)(b * S_ + q0 + r) * 1024 + h * 64 + dcol;
            *reinterpret_cast<uint32_t*>(dst) = hh;
            *reinterpret_cast<uint32_t*>(dst + 512) = ll;
        }
    }
}

// ---------------------------------------------------------------------------
extern "C" void kernel_launch(void* const* d_in, const int* in_sizes, int n_in,
                              void* d_out, int out_size)
{
    const float* x  = (const float*)d_in[0];
    const float* Wq = (const float*)d_in[1];
    const float* bq = (const float*)d_in[2];
    const float* Wk = (const float*)d_in[3];
    const float* bk = (const float*)d_in[4];
    const float* Wv = (const float*)d_in[5];
    const float* bv = (const float*)d_in[6];
    const float* Wo = (const float*)d_in[7];
    const float* bo = (const float*)d_in[8];
    const int* xlen = (const int*)d_in[9];
    float* out = (float*)d_out;

    void* px2;
    cudaGetSymbolAddress(&px2, g_x2);

    cudaFuncSetAttribute(qkv_gemm_tc_b,
                         cudaFuncAttributeMaxDynamicSharedMemorySize,
                         GEMM_SMEM_BYTES);
    cudaFuncSetAttribute(out_gemm_tc,
                         cudaFuncAttributeMaxDynamicSharedMemorySize,
                         GEMM_SMEM_BYTES);
    cudaFuncSetAttribute(attn_kernel,
                         cudaFuncAttributeMaxDynamicSharedMemorySize,
                         ATTN_SMEM_BYTES);

    split_a<<<M_ * DM_ / 1024, 256>>>(x, (__nv_bfloat16*)px2);
    split_w<<<dim3(16, 16, 4), 256>>>(Wq, Wk, Wv, Wo);
    stage_bias<<<2, 256>>>(bq, bk, bv);

    qkv_gemm_tc_b<<<dim3(DM_ / 128, M_ / 128, 3), 256, GEMM_SMEM_BYTES>>>();

    vmean1<<<dim3(B_ * H_, 8), 256>>>();
    vmean2<<<B_ * H_, 64>>>();

    attn_kernel<<<dim3(S_ / 64, H_, B_), 256, ATTN_SMEM_BYTES>>>(xlen);

    out_gemm_tc<<<dim3(DM_ / 128, M_ / 128), 256, GEMM_SMEM_BYTES>>>(bo, out);
}